// round 14
// baseline (speedup 1.0000x reference)
#include <cuda_runtime.h>
#include <cuda.h>
#include <cuda_fp16.h>
#include <cstdint>

// Problem dims
#define NM 64
#define NK 4096
#define NW 14336
#define NTILE 128           // N columns per CTA
#define KC2 64              // K per stage
#define NIT2 64             // NK/KC2
#define NBLK 112            // NW/NTILE
#define THREADS 256
#define STAGES 4

// SMEM: 4 stages x (W int32 32KB [4 boxes of 32n x 64k, SW128] + A fp16 8KB)
#define BUFSZ 40960
#define XOFF  32768
#define SM_MB (STAGES * BUFSZ)          // 4 full-barriers (8B each)
#define SMEM_TOTAL (SM_MB + STAGES * 8)

// Global scratch: pre-swizzled fp16 x image (64 stages x 8KB) + rowsum (fp16-rounded x)
__device__ __align__(16) unsigned char g_ximg[NIT2 * 8192];
__device__ __align__(16) float g_rs4[NM * 4];

// ---------------- helpers ----------------
__device__ __forceinline__ uint32_t smem_u32(const void* p) {
    uint32_t a;
    asm("{ .reg .u64 t; cvta.to.shared.u64 t, %1; cvt.u32.u64 %0, t; }" : "=r"(a) : "l"(p));
    return a;
}

#define MBARRIER_INIT(addr, cnt) \
    asm volatile("mbarrier.init.shared.b64 [%0], %1;" :: "r"((uint32_t)(addr)), "r"((uint32_t)(cnt)) : "memory")

#define MBARRIER_EXPECT_TX(addr, bytes) \
    asm volatile("mbarrier.arrive.expect_tx.shared.b64 _, [%0], %1;" \
        :: "r"((uint32_t)(addr)), "r"((uint32_t)(bytes)) : "memory")

#define MBARRIER_WAIT_PARITY(mbar, par) do {                                        \
    uint32_t _m = (uint32_t)(mbar); uint32_t _p = (uint32_t)(par); uint32_t _d;     \
    asm volatile("{ .reg .pred p;\n"                                                \
        "mbarrier.try_wait.parity.acquire.cta.shared::cta.b64 p, [%1], %2;\n"       \
        "selp.b32 %0, 1, 0, p; }"                                                   \
        : "=r"(_d) : "r"(_m), "r"(_p) : "memory");                                  \
    if (!_d) {                                                                      \
        asm volatile("{ .reg .pred P1;\n"                                           \
            "WL_%=:\n"                                                              \
            "mbarrier.try_wait.parity.acquire.cta.shared::cta.b64 P1, [%0], %1, 0x989680;\n" \
            "@P1 bra.uni WD_%=;\n"                                                  \
            "bra.uni WL_%=;\n"                                                      \
            "WD_%=: }" :: "r"(_m), "r"(_p) : "memory");                             \
    }                                                                               \
} while (0)

__device__ __forceinline__ void tma_2d(uint32_t dst, const void* map, int cx, int cy, uint32_t mbar) {
    asm volatile(
        "cp.async.bulk.tensor.2d.shared::cluster.global.tile.mbarrier::complete_tx::bytes "
        "[%0], [%1, {%2, %3}], [%4];"
        :: "r"(dst), "l"(map), "r"(cx), "r"(cy), "r"(mbar) : "memory");
}
__device__ __forceinline__ void bulk_g2s(uint32_t dst, const void* src, uint32_t bytes, uint32_t mbar) {
    asm volatile(
        "cp.async.bulk.shared::cluster.global.mbarrier::complete_tx::bytes "
        "[%0], [%1], %2, [%3];"
        :: "r"(dst), "l"(src), "r"(bytes), "r"(mbar) : "memory");
}
__device__ __forceinline__ void ldmatrix_x4(uint32_t* r, uint32_t addr) {
    asm volatile("ldmatrix.sync.aligned.m8n8.x4.shared.b16 {%0,%1,%2,%3}, [%4];"
        : "=r"(r[0]), "=r"(r[1]), "=r"(r[2]), "=r"(r[3]) : "r"(addr));
}
__device__ __forceinline__ uint32_t lds32(uint32_t addr) {
    uint32_t v;
    asm volatile("ld.shared.b32 %0, [%1];" : "=r"(v) : "r"(addr));
    return v;
}
// fp16x2 of (1152 + w0, 1152 + w1) from two int32 weights in [-128,128): PRMT + LOP3
__device__ __forceinline__ uint32_t magic_pack(uint32_t v0, uint32_t v1) {
    uint32_t p = __byte_perm(v0, v1, 0x0400);       // {v0.b0, *, v1.b0, *}
    return (p & 0x00FF00FFu) ^ 0x64806480u;         // halves: 0x6400 | ((v+128)&0xFF)
}
__device__ __forceinline__ void mma16816(float* d, const uint32_t* a, const uint32_t* b) {
    asm volatile(
        "mma.sync.aligned.m16n8k16.row.col.f32.f16.f16.f32 "
        "{%0,%1,%2,%3}, {%4,%5,%6,%7}, {%8,%9}, {%0,%1,%2,%3};"
        : "+f"(d[0]), "+f"(d[1]), "+f"(d[2]), "+f"(d[3])
        : "r"(a[0]), "r"(a[1]), "r"(a[2]), "r"(a[3]), "r"(b[0]), "r"(b[1]));
}

// ---------------- prep: x -> fp16 image + rowsum over fp16-rounded x ----------------
// stage hc (8KB): addr = hc*8192 + m*128 + (((k&63)*2) ^ ((m&7)<<4))
__global__ void prep(const float* __restrict__ x) {
    __shared__ float red[4];
    const int m = blockIdx.x >> 2;
    const int kq = blockIdx.x & 3;
    const int t = threadIdx.x;              // 128 threads x 8 k
    const int k = kq * 1024 + t * 8;
    const float4* xp = reinterpret_cast<const float4*>(x + (size_t)m * NK + k);
    float4 a = xp[0], b = xp[1];
    float v[8] = {a.x, a.y, a.z, a.w, b.x, b.y, b.z, b.w};
    __align__(16) __half h[8];
    float s = 0.f;
#pragma unroll
    for (int i = 0; i < 8; i++) { h[i] = __float2half_rn(v[i]); s += __half2float(h[i]); }
    uint32_t off = (uint32_t)(k >> 6) * 8192u + (uint32_t)m * 128u
                 + ((((uint32_t)k & 63u) * 2u) ^ (((uint32_t)m & 7u) << 4));
    *reinterpret_cast<uint4*>(g_ximg + off) = *reinterpret_cast<uint4*>(h);
#pragma unroll
    for (int o = 16; o; o >>= 1) s += __shfl_xor_sync(0xffffffffu, s, o);
    if ((t & 31) == 0) red[t >> 5] = s;
    __syncthreads();
    if (t == 0) g_rs4[m * 4 + kq] = red[0] + red[1] + red[2] + red[3];
}

// ---------------- main kernel ----------------
__global__ __launch_bounds__(THREADS, 1) void wqmm_main(
    const __grid_constant__ CUtensorMap tmw,
    const float* __restrict__ scale,
    const float* __restrict__ offs,
    const float* __restrict__ bias,
    float* __restrict__ out)
{
    extern __shared__ char smem[];
    const uint32_t sb = smem_u32(smem);
    const int tid = threadIdx.x;
    const int wid = tid >> 5;
    const int lane = tid & 31;
    const int n0 = blockIdx.x * NTILE;

    if (tid == 0) {
#pragma unroll
        for (int s = 0; s < STAGES; s++) MBARRIER_INIT(sb + SM_MB + s * 8, 1);
        asm volatile("fence.mbarrier_init.release.cluster;" ::: "memory");
    }
    __syncthreads();

    // issue loads for stage-chunk c into ring slot st (single thread)
    auto issue = [&](int c, int st) {
        const uint32_t mb = sb + SM_MB + (uint32_t)st * 8;
        const uint32_t wdst = sb + (uint32_t)st * BUFSZ;
        MBARRIER_EXPECT_TX(mb, 40960);
#pragma unroll
        for (int bx = 0; bx < 4; bx++)
            tma_2d(wdst + (uint32_t)bx * 8192, &tmw, n0 + bx * 32, c * KC2, mb);
        bulk_g2s(wdst + XOFF, g_ximg + (size_t)c * 8192, 8192, mb);
    };
    if (tid == 0) {
#pragma unroll
        for (int s = 0; s < STAGES; s++) issue(s, s);
    }

    // ---- warp grid: kh(2) x nw(4); warp tile m64 x n32 x k32 ----
    const int kh = wid >> 2;            // 0..1 : k-half of stage
    const int nw = wid & 3;             // 0..3 -> TMA box nw
    const int g = lane >> 2;
    const int tg = lane & 3;

    // A ldmatrix (128B rows): base row = (lane&8) + (lane&7); m-tile mt adds mt*16 rows (+2048B)
    const uint32_t aoff = (uint32_t)((lane & 8) + (lane & 7)) * 128u;
    const uint32_t aswx = ((uint32_t)(lane & 7)) << 4;
    const uint32_t akq = ((uint32_t)((lane >> 4) & 1)) * 16u + (uint32_t)kh * 64u;

    // B int32 LDS offsets within box: nl = nt*8 + g
    uint32_t c0[4], c1[4];
#pragma unroll
    for (int nt = 0; nt < 4; nt++) {
        uint32_t nl = (uint32_t)(nt * 8 + g);
        c0[nt] = (nl * 4u) ^ (((uint32_t)(tg * 2)) << 4);
        c1[nt] = (nl * 4u) ^ (((uint32_t)(tg * 2 + 1)) << 4);
    }
    const uint32_t bbase = (uint32_t)nw * 8192u + (uint32_t)kh * 4096u + (uint32_t)(tg * 2) * 128u;

    float acc[4][4][4];                 // [m-tile][n-tile][frag]
#pragma unroll
    for (int i = 0; i < 4; i++)
#pragma unroll
        for (int j = 0; j < 4; j++)
#pragma unroll
            for (int q = 0; q < 4; q++) acc[i][j][q] = 0.f;

    // consume one resident stage
    auto consume = [&](int st) {
        const uint32_t wb = sb + (uint32_t)st * BUFSZ;
        const uint32_t xb = wb + XOFF;
#pragma unroll
        for (int ks = 0; ks < 2; ks++) {
            uint32_t a0[4], a1[4], a2[4], a3[4];
            const uint32_t xaddr = xb + aoff + (((uint32_t)(ks * 32) + akq) ^ aswx);
            ldmatrix_x4(a0, xaddr);
            ldmatrix_x4(a1, xaddr + 2048);
            ldmatrix_x4(a2, xaddr + 4096);
            ldmatrix_x4(a3, xaddr + 6144);

            const uint32_t kb = wb + bbase + (uint32_t)ks * 2048u;
#pragma unroll
            for (int nt = 0; nt < 4; nt++) {
                uint32_t w00 = lds32(kb + c0[nt]);          // k,   n
                uint32_t w01 = lds32(kb + 128 + c1[nt]);    // k+1
                uint32_t w08 = lds32(kb + 1024 + c0[nt]);   // k+8
                uint32_t w09 = lds32(kb + 1152 + c1[nt]);   // k+9
                uint32_t bfr[2];
                bfr[0] = magic_pack(w00, w01);              // fp16x2 (1152+w)
                bfr[1] = magic_pack(w08, w09);
                mma16816(acc[0][nt], a0, bfr);
                mma16816(acc[1][nt], a1, bfr);
                mma16816(acc[2][nt], a2, bfr);
                mma16816(acc[3][nt], a3, bfr);
            }
        }
    };

    // main loop: two beats per CTA barrier; refill both consumed slots after sync
    for (int it = 0; it < NIT2; it += 2) {
        const int st0 = it & 3, st1 = (it + 1) & 3;
        const uint32_t par = (uint32_t)((it >> 2) & 1);     // it, it+1 share a quad
        MBARRIER_WAIT_PARITY(sb + SM_MB + st0 * 8, par);
        consume(st0);
        MBARRIER_WAIT_PARITY(sb + SM_MB + st1 * 8, par);
        consume(st1);
        __syncthreads();
        if (tid == 0 && it + 4 < NIT2) { issue(it + 4, st0); issue(it + 5, st1); }
    }

    // ---- k-split merge through SMEM (reuse stage-0 buffer, 32KB) ----
    float* sc = reinterpret_cast<float*>(smem);
    if (kh == 1) {
#pragma unroll
        for (int nt = 0; nt < 4; nt++) {
            const int nl = nw * 32 + nt * 8 + tg * 2;
#pragma unroll
            for (int mt = 0; mt < 4; mt++) {
                const int m = mt * 16 + g;
                *reinterpret_cast<float2*>(sc + m * 128 + nl) =
                    make_float2(acc[mt][nt][0], acc[mt][nt][1]);
                *reinterpret_cast<float2*>(sc + (m + 8) * 128 + nl) =
                    make_float2(acc[mt][nt][2], acc[mt][nt][3]);
            }
        }
    }
    __syncthreads();
    if (kh == 0) {
        // ---- epilogue: out = s*(accL+accH) + s*(off-1152)*rowsum + bias ----
#pragma unroll
        for (int nt = 0; nt < 4; nt++) {
            const int nl = nw * 32 + nt * 8 + tg * 2;
            const int n = n0 + nl;
            const float s0 = scale[n], s1 = scale[n + 1];
            const float t0 = s0 * (offs[n] - 1152.0f), t1 = s1 * (offs[n + 1] - 1152.0f);
            const float b0 = bias[n], b1 = bias[n + 1];
#pragma unroll
            for (int mt = 0; mt < 4; mt++) {
                const int m = mt * 16 + g;
                const float4 ra = *reinterpret_cast<const float4*>(g_rs4 + (size_t)m * 4);
                const float4 rb = *reinterpret_cast<const float4*>(g_rs4 + (size_t)(m + 8) * 4);
                const float r0 = (ra.x + ra.y) + (ra.z + ra.w);
                const float r1 = (rb.x + rb.y) + (rb.z + rb.w);
                const float2 h0 = *reinterpret_cast<const float2*>(sc + m * 128 + nl);
                const float2 h1 = *reinterpret_cast<const float2*>(sc + (m + 8) * 128 + nl);
                float2 v0, v1;
                v0.x = fmaf(acc[mt][nt][0] + h0.x, s0, fmaf(t0, r0, b0));
                v0.y = fmaf(acc[mt][nt][1] + h0.y, s1, fmaf(t1, r0, b1));
                v1.x = fmaf(acc[mt][nt][2] + h1.x, s0, fmaf(t0, r1, b0));
                v1.y = fmaf(acc[mt][nt][3] + h1.y, s1, fmaf(t1, r1, b1));
                *reinterpret_cast<float2*>(out + (size_t)m * NW + n) = v0;
                *reinterpret_cast<float2*>(out + (size_t)(m + 8) * NW + n) = v1;
            }
        }
    }
}

// ---------------- launch ----------------
typedef CUresult (*EncodeFn)(CUtensorMap*, CUtensorMapDataType, cuuint32_t, void*,
    const cuuint64_t*, const cuuint64_t*, const cuuint32_t*, const cuuint32_t*,
    CUtensorMapInterleave, CUtensorMapSwizzle, CUtensorMapL2promotion, CUtensorMapFloatOOBfill);

extern "C" void kernel_launch(void* const* d_in, const int* in_sizes, int n_in,
                              void* d_out, int out_size) {
    const float* x     = (const float*)d_in[0];
    void*        w     = (void*)d_in[1];
    const float* scale = (const float*)d_in[2];
    const float* offs  = (const float*)d_in[3];
    const float* bias  = (const float*)d_in[4];
    float* out = (float*)d_out;

    void* sym = nullptr;
    cudaDriverEntryPointQueryResult qr;
#if CUDART_VERSION >= 12050
    cudaGetDriverEntryPointByVersion("cuTensorMapEncodeTiled", &sym, 12000, cudaEnableDefault, &qr);
#else
    cudaGetDriverEntryPoint("cuTensorMapEncodeTiled", &sym, cudaEnableDefault, &qr);
#endif
    EncodeFn enc = (EncodeFn)sym;

    CUtensorMap tmw;
    cuuint64_t dims[2]    = {(cuuint64_t)NW, (cuuint64_t)NK};
    cuuint64_t strides[1] = {(cuuint64_t)NW * 4};
    cuuint32_t box[2]     = {32u, 64u};
    cuuint32_t es[2]      = {1u, 1u};
    enc(&tmw, CU_TENSOR_MAP_DATA_TYPE_UINT32, 2, w, dims, strides, box, es,
        CU_TENSOR_MAP_INTERLEAVE_NONE, CU_TENSOR_MAP_SWIZZLE_128B,
        CU_TENSOR_MAP_L2_PROMOTION_L2_128B, CU_TENSOR_MAP_FLOAT_OOB_FILL_NONE);

    cudaFuncSetAttribute(wqmm_main, cudaFuncAttributeMaxDynamicSharedMemorySize, SMEM_TOTAL);

    prep<<<NM * 4, 128>>>(x);
    wqmm_main<<<NBLK, THREADS, SMEM_TOTAL>>>(tmw, scale, offs, bias, out);
}

// round 15
// speedup vs baseline: 1.0907x; 1.0907x over previous
#include <cuda_runtime.h>
#include <cuda.h>
#include <cuda_fp16.h>
#include <cstdint>

// Problem dims
#define NM 64
#define NK 4096
#define NW 14336
#define NTILE 128           // N columns per CTA
#define KC2 64              // K per stage
#define NIT2 64             // NK/KC2
#define NBLK 112            // NW/NTILE
#define THREADS 288         // 8 consumer warps + 1 producer warp
#define STAGES 5

// SMEM: 5 stages x (W int32 32KB [4 boxes of 32n x 64k, SW128] + A fp16 8KB)
#define BUFSZ 40960
#define XOFF  32768
#define SM_MB (STAGES * BUFSZ)          // 5 x {full,empty} pairs (16B each)
#define SMEM_TOTAL (SM_MB + STAGES * 16)

// Global scratch: pre-swizzled fp16 x image (64 stages x 8KB) + rowsum (fp16-rounded x)
__device__ __align__(16) unsigned char g_ximg[NIT2 * 8192];
__device__ __align__(16) float g_rs4[NM * 4];

// ---------------- helpers ----------------
__device__ __forceinline__ uint32_t smem_u32(const void* p) {
    uint32_t a;
    asm("{ .reg .u64 t; cvta.to.shared.u64 t, %1; cvt.u32.u64 %0, t; }" : "=r"(a) : "l"(p));
    return a;
}

#define MBARRIER_INIT(addr, cnt) \
    asm volatile("mbarrier.init.shared.b64 [%0], %1;" :: "r"((uint32_t)(addr)), "r"((uint32_t)(cnt)) : "memory")

#define MBARRIER_EXPECT_TX(addr, bytes) \
    asm volatile("mbarrier.arrive.expect_tx.shared.b64 _, [%0], %1;" \
        :: "r"((uint32_t)(addr)), "r"((uint32_t)(bytes)) : "memory")

#define MBARRIER_ARRIVE(addr) \
    asm volatile("mbarrier.arrive.release.cta.shared::cta.b64 _, [%0];" :: "r"((uint32_t)(addr)) : "memory")

#define MBARRIER_WAIT_PARITY(mbar, par) do {                                        \
    uint32_t _m = (uint32_t)(mbar); uint32_t _p = (uint32_t)(par); uint32_t _d;     \
    asm volatile("{ .reg .pred p;\n"                                                \
        "mbarrier.try_wait.parity.acquire.cta.shared::cta.b64 p, [%1], %2;\n"       \
        "selp.b32 %0, 1, 0, p; }"                                                   \
        : "=r"(_d) : "r"(_m), "r"(_p) : "memory");                                  \
    if (!_d) {                                                                      \
        asm volatile("{ .reg .pred P1;\n"                                           \
            "WL_%=:\n"                                                              \
            "mbarrier.try_wait.parity.acquire.cta.shared::cta.b64 P1, [%0], %1, 0x989680;\n" \
            "@P1 bra.uni WD_%=;\n"                                                  \
            "bra.uni WL_%=;\n"                                                      \
            "WD_%=: }" :: "r"(_m), "r"(_p) : "memory");                             \
    }                                                                               \
} while (0)

__device__ __forceinline__ void tma_2d(uint32_t dst, const void* map, int cx, int cy, uint32_t mbar) {
    asm volatile(
        "cp.async.bulk.tensor.2d.shared::cluster.global.tile.mbarrier::complete_tx::bytes "
        "[%0], [%1, {%2, %3}], [%4];"
        :: "r"(dst), "l"(map), "r"(cx), "r"(cy), "r"(mbar) : "memory");
}
__device__ __forceinline__ void bulk_g2s(uint32_t dst, const void* src, uint32_t bytes, uint32_t mbar) {
    asm volatile(
        "cp.async.bulk.shared::cluster.global.mbarrier::complete_tx::bytes "
        "[%0], [%1], %2, [%3];"
        :: "r"(dst), "l"(src), "r"(bytes), "r"(mbar) : "memory");
}
__device__ __forceinline__ void ldmatrix_x4(uint32_t* r, uint32_t addr) {
    asm volatile("ldmatrix.sync.aligned.m8n8.x4.shared.b16 {%0,%1,%2,%3}, [%4];"
        : "=r"(r[0]), "=r"(r[1]), "=r"(r[2]), "=r"(r[3]) : "r"(addr));
}
__device__ __forceinline__ uint32_t lds32(uint32_t addr) {
    uint32_t v;
    asm volatile("ld.shared.b32 %0, [%1];" : "=r"(v) : "r"(addr));
    return v;
}
// fp16x2 of (1152 + w0, 1152 + w1) from two int32 weights in [-128,128): PRMT + LOP3
__device__ __forceinline__ uint32_t magic_pack(uint32_t v0, uint32_t v1) {
    uint32_t p = __byte_perm(v0, v1, 0x0400);       // {v0.b0, *, v1.b0, *}
    return (p & 0x00FF00FFu) ^ 0x64806480u;         // halves: 0x6400 | ((v+128)&0xFF)
}
__device__ __forceinline__ void mma16816(float* d, const uint32_t* a, const uint32_t* b) {
    asm volatile(
        "mma.sync.aligned.m16n8k16.row.col.f32.f16.f16.f32 "
        "{%0,%1,%2,%3}, {%4,%5,%6,%7}, {%8,%9}, {%0,%1,%2,%3};"
        : "+f"(d[0]), "+f"(d[1]), "+f"(d[2]), "+f"(d[3])
        : "r"(a[0]), "r"(a[1]), "r"(a[2]), "r"(a[3]), "r"(b[0]), "r"(b[1]));
}

// ---------------- prep: x -> fp16 image + rowsum over fp16-rounded x ----------------
// stage hc (8KB): addr = hc*8192 + m*128 + (((k&63)*2) ^ ((m&7)<<4))
__global__ void prep(const float* __restrict__ x) {
    __shared__ float red[4];
    const int m = blockIdx.x >> 2;
    const int kq = blockIdx.x & 3;
    const int t = threadIdx.x;              // 128 threads x 8 k
    const int k = kq * 1024 + t * 8;
    const float4* xp = reinterpret_cast<const float4*>(x + (size_t)m * NK + k);
    float4 a = xp[0], b = xp[1];
    float v[8] = {a.x, a.y, a.z, a.w, b.x, b.y, b.z, b.w};
    __align__(16) __half h[8];
    float s = 0.f;
#pragma unroll
    for (int i = 0; i < 8; i++) { h[i] = __float2half_rn(v[i]); s += __half2float(h[i]); }
    uint32_t off = (uint32_t)(k >> 6) * 8192u + (uint32_t)m * 128u
                 + ((((uint32_t)k & 63u) * 2u) ^ (((uint32_t)m & 7u) << 4));
    *reinterpret_cast<uint4*>(g_ximg + off) = *reinterpret_cast<uint4*>(h);
#pragma unroll
    for (int o = 16; o; o >>= 1) s += __shfl_xor_sync(0xffffffffu, s, o);
    if ((t & 31) == 0) red[t >> 5] = s;
    __syncthreads();
    if (t == 0) g_rs4[m * 4 + kq] = red[0] + red[1] + red[2] + red[3];
}

// ---------------- main kernel ----------------
__global__ __launch_bounds__(THREADS, 1) void wqmm_main(
    const __grid_constant__ CUtensorMap tmw,
    const float* __restrict__ scale,
    const float* __restrict__ offs,
    const float* __restrict__ bias,
    float* __restrict__ out)
{
    extern __shared__ char smem[];
    const uint32_t sb = smem_u32(smem);
    const int tid = threadIdx.x;
    const int wid = tid >> 5;
    const int lane = tid & 31;
    const int n0 = blockIdx.x * NTILE;

    if (tid == 0) {
#pragma unroll
        for (int s = 0; s < STAGES; s++) {
            MBARRIER_INIT(sb + SM_MB + s * 16 + 0, 1);    // full[s]: TMA tx
            MBARRIER_INIT(sb + SM_MB + s * 16 + 8, 8);    // empty[s]: 8 consumer-warp arrivals
        }
        asm volatile("fence.mbarrier_init.release.cluster;" ::: "memory");
    }
    __syncthreads();

    if (wid == 8) {
        // ================= producer warp =================
        if (lane == 0) {
            // prologue: fill all 5 slots
#pragma unroll
            for (int s = 0; s < STAGES; s++) {
                const uint32_t mb = sb + SM_MB + (uint32_t)s * 16;
                const uint32_t wdst = sb + (uint32_t)s * BUFSZ;
                MBARRIER_EXPECT_TX(mb, 40960);
#pragma unroll
                for (int bx = 0; bx < 4; bx++)
                    tma_2d(wdst + (uint32_t)bx * 8192, &tmw, n0 + bx * 32, s * KC2, mb);
                bulk_g2s(wdst + XOFF, g_ximg + (size_t)s * 8192, 8192, mb);
            }
            // steady state: refill slot c%5 as soon as consumers release it
            int st = 0, pph = 0;    // empty-wait parity for use u: (u-1)&1; u=1 first
            for (int c = STAGES; c < NIT2; ++c) {
                MBARRIER_WAIT_PARITY(sb + SM_MB + st * 16 + 8, pph);
                const uint32_t mb = sb + SM_MB + (uint32_t)st * 16;
                const uint32_t wdst = sb + (uint32_t)st * BUFSZ;
                MBARRIER_EXPECT_TX(mb, 40960);
#pragma unroll
                for (int bx = 0; bx < 4; bx++)
                    tma_2d(wdst + (uint32_t)bx * 8192, &tmw, n0 + bx * 32, c * KC2, mb);
                bulk_g2s(wdst + XOFF, g_ximg + (size_t)c * 8192, 8192, mb);
                if (++st == STAGES) { st = 0; pph ^= 1; }
            }
        }
        return;
    }

    // ================= consumers (warps 0-7): mw(2) x nw(4), m32 x n32 x k64 tiles =================
    const int mw = wid >> 2;            // 0..1
    const int nw = wid & 3;             // 0..3 -> TMA box nw
    const int g = lane >> 2;
    const int tg = lane & 3;

    // A ldmatrix (128B rows): row = mw*32 + (lane&8) + (lane&7)
    const uint32_t aoff = (uint32_t)(mw * 32 + (lane & 8) + (lane & 7)) * 128u;
    const uint32_t aswx = ((uint32_t)(lane & 7)) << 4;
    const uint32_t akq = ((uint32_t)((lane >> 4) & 1)) * 16u;

    // B int32 LDS offsets within box: nl = nt*8 + g
    uint32_t c0[4], c1[4];
#pragma unroll
    for (int nt = 0; nt < 4; nt++) {
        uint32_t nl = (uint32_t)(nt * 8 + g);
        c0[nt] = (nl * 4u) ^ (((uint32_t)(tg * 2)) << 4);
        c1[nt] = (nl * 4u) ^ (((uint32_t)(tg * 2 + 1)) << 4);
    }
    const uint32_t bbase = (uint32_t)nw * 8192u + (uint32_t)(tg * 2) * 128u;

    float acc[2][4][4];
#pragma unroll
    for (int i = 0; i < 2; i++)
#pragma unroll
        for (int j = 0; j < 4; j++)
#pragma unroll
            for (int q = 0; q < 4; q++) acc[i][j][q] = 0.f;

    int st = 0, ph = 0;
    for (int it = 0; it < NIT2; ++it) {
        MBARRIER_WAIT_PARITY(sb + SM_MB + st * 16, ph);

        const uint32_t wb = sb + (uint32_t)st * BUFSZ;
        const uint32_t xb = wb + XOFF;

#pragma unroll
        for (int ks = 0; ks < 4; ks++) {
            uint32_t a0[4], a1[4];
            const uint32_t xaddr = xb + aoff + (((uint32_t)(ks * 32) + akq) ^ aswx);
            ldmatrix_x4(a0, xaddr);
            ldmatrix_x4(a1, xaddr + 2048);      // +16 m-rows

            const uint32_t kb = wb + bbase + (uint32_t)ks * 2048u;
#pragma unroll
            for (int nt = 0; nt < 4; nt++) {
                uint32_t w00 = lds32(kb + c0[nt]);          // k,   n
                uint32_t w01 = lds32(kb + 128 + c1[nt]);    // k+1
                uint32_t w08 = lds32(kb + 1024 + c0[nt]);   // k+8
                uint32_t w09 = lds32(kb + 1152 + c1[nt]);   // k+9
                uint32_t bfr[2];
                bfr[0] = magic_pack(w00, w01);              // fp16x2 (1152+w)
                bfr[1] = magic_pack(w08, w09);
                mma16816(acc[0][nt], a0, bfr);
                mma16816(acc[1][nt], a1, bfr);
            }
        }

        __syncwarp();
        if (lane == 0) MBARRIER_ARRIVE(sb + SM_MB + st * 16 + 8);   // release slot
        if (++st == STAGES) { st = 0; ph ^= 1; }
    }

    // ---- epilogue: out = s*acc + s*(off-1152)*rowsum + bias ----
#pragma unroll
    for (int nt = 0; nt < 4; nt++) {
        const int n = n0 + nw * 32 + nt * 8 + tg * 2;
        const float s0 = scale[n], s1 = scale[n + 1];
        const float t0 = s0 * (offs[n] - 1152.0f), t1 = s1 * (offs[n + 1] - 1152.0f);
        const float b0 = bias[n], b1 = bias[n + 1];
#pragma unroll
        for (int mt = 0; mt < 2; mt++) {
            const int m = mw * 32 + mt * 16 + g;
            const float4 ra = *reinterpret_cast<const float4*>(g_rs4 + (size_t)m * 4);
            const float4 rb = *reinterpret_cast<const float4*>(g_rs4 + (size_t)(m + 8) * 4);
            const float r0 = (ra.x + ra.y) + (ra.z + ra.w);
            const float r1 = (rb.x + rb.y) + (rb.z + rb.w);
            float2 v0, v1;
            v0.x = fmaf(acc[mt][nt][0], s0, fmaf(t0, r0, b0));
            v0.y = fmaf(acc[mt][nt][1], s1, fmaf(t1, r0, b1));
            v1.x = fmaf(acc[mt][nt][2], s0, fmaf(t0, r1, b0));
            v1.y = fmaf(acc[mt][nt][3], s1, fmaf(t1, r1, b1));
            *reinterpret_cast<float2*>(out + (size_t)m * NW + n) = v0;
            *reinterpret_cast<float2*>(out + (size_t)(m + 8) * NW + n) = v1;
        }
    }
}

// ---------------- launch ----------------
typedef CUresult (*EncodeFn)(CUtensorMap*, CUtensorMapDataType, cuuint32_t, void*,
    const cuuint64_t*, const cuuint64_t*, const cuuint32_t*, const cuuint32_t*,
    CUtensorMapInterleave, CUtensorMapSwizzle, CUtensorMapL2promotion, CUtensorMapFloatOOBfill);

extern "C" void kernel_launch(void* const* d_in, const int* in_sizes, int n_in,
                              void* d_out, int out_size) {
    const float* x     = (const float*)d_in[0];
    void*        w     = (void*)d_in[1];
    const float* scale = (const float*)d_in[2];
    const float* offs  = (const float*)d_in[3];
    const float* bias  = (const float*)d_in[4];
    float* out = (float*)d_out;

    void* sym = nullptr;
    cudaDriverEntryPointQueryResult qr;
#if CUDART_VERSION >= 12050
    cudaGetDriverEntryPointByVersion("cuTensorMapEncodeTiled", &sym, 12000, cudaEnableDefault, &qr);
#else
    cudaGetDriverEntryPoint("cuTensorMapEncodeTiled", &sym, cudaEnableDefault, &qr);
#endif
    EncodeFn enc = (EncodeFn)sym;

    CUtensorMap tmw;
    cuuint64_t dims[2]    = {(cuuint64_t)NW, (cuuint64_t)NK};
    cuuint64_t strides[1] = {(cuuint64_t)NW * 4};
    cuuint32_t box[2]     = {32u, 64u};
    cuuint32_t es[2]      = {1u, 1u};
    enc(&tmw, CU_TENSOR_MAP_DATA_TYPE_UINT32, 2, w, dims, strides, box, es,
        CU_TENSOR_MAP_INTERLEAVE_NONE, CU_TENSOR_MAP_SWIZZLE_128B,
        CU_TENSOR_MAP_L2_PROMOTION_L2_128B, CU_TENSOR_MAP_FLOAT_OOB_FILL_NONE);

    cudaFuncSetAttribute(wqmm_main, cudaFuncAttributeMaxDynamicSharedMemorySize, SMEM_TOTAL);

    prep<<<NM * 4, 128>>>(x);
    wqmm_main<<<NBLK, THREADS, SMEM_TOTAL>>>(tmw, scale, offs, bias, out);
}